// round 6
// baseline (speedup 1.0000x reference)
#include <cuda_runtime.h>

#define CIN   64
#define CO    64
#define FEAT  1152
#define N1    576
#define N2    4096
#define HW    128
#define TILE  32
#define NTH   512
#define FSP   36
#define PER_TENSOR (4 * CO * HW * HW)

#define SMEM_FLOATS (FEAT * FSP + 3 * TILE * 64)
#define SMEM_BYTES  (SMEM_FLOATS * 4)    // 190,464 B

typedef unsigned long long ull;

// packed duplicated weights:
// W1pd[f][ch=0..4][c=0..63][4]   taps {2ch,2ch+1} each duplicated  (5.9 MB)
// W2pd[cg][f][ch=0..1][colB][4]  cols {cg*512+(2ch+i/2)*128+colB} dup (37.7 MB)
__device__ float W1pd[FEAT * 5 * 64 * 4];
__device__ float W2pd[8LL * FEAT * 2 * 128 * 4];

__global__ void pack_w1(const float* __restrict__ W1) {
    int idx = blockIdx.x * blockDim.x + threadIdx.x;
    if (idx >= FEAT * 5 * 64 * 4) return;
    int i  = idx & 3;
    int c  = (idx >> 2) & 63;
    int ch = (idx >> 8) % 5;
    int f  = idx / 1280;
    int tap = ch * 2 + (i >> 1);
    W1pd[idx] = (tap < 9) ? W1[(size_t)f * N1 + c * 9 + tap] : 0.0f;
}

__global__ void pack_w2(const float* __restrict__ W2) {
    long long idx = (long long)blockIdx.x * blockDim.x + threadIdx.x;
    if (idx >= 8LL * FEAT * 2 * 128 * 4) return;
    int i    = (int)(idx & 3);
    int colB = (int)((idx >> 2) & 127);
    int ch   = (int)((idx >> 9) & 1);
    int f    = (int)((idx >> 10) % FEAT);
    int cg   = (int)(idx / (1024LL * FEAT));
    int col  = cg * 512 + (ch * 2 + (i >> 1)) * 128 + colB;
    W2pd[idx] = W2[(size_t)f * N2 + col];
}

__device__ __forceinline__ void fma2(ull& a, ull x, ull y) {
    asm("fma.rn.f32x2 %0, %1, %2, %0;" : "+l"(a) : "l"(x), "l"(y));
}
__device__ __forceinline__ float2 unpk(ull v) {
    float2 f; asm("mov.b64 {%0, %1}, %2;" : "=f"(f.x), "=f"(f.y) : "l"(v)); return f;
}

__global__ __launch_bounds__(NTH, 1)
void fused_kpn_kernel(const float* __restrict__ x,
                      const float* __restrict__ m,
                      const float* __restrict__ s,
                      const float* __restrict__ b1,
                      const float* __restrict__ b2,
                      float* __restrict__ out)
{
    extern __shared__ float smf[];
    float* featT = smf;                       // [FEAT][FSP]
    float* yr_s  = smf + FEAT * FSP;          // [32][64]
    float* mr_s  = yr_s + TILE * 64;
    float* sr_s  = mr_s + TILE * 64;

    const int tid  = threadIdx.x;
    const int pix0 = blockIdx.x * TILE;
    const int b    = pix0 >> 14;
    const int h    = (pix0 >> 7) & 127;
    const int w0   = pix0 & 127;

    // ---- gather feat tile (transposed): featT[f][pix] ----
    const float* base_x = x + (size_t)b * (CIN * HW * HW);
    const float* base_m = m + (size_t)b * (CIN * HW * HW);
    for (int idx = tid; idx < TILE * FEAT; idx += NTH) {
        int pix = idx & 31;
        int f   = idx >> 5;
        const float* src = base_x;
        int fr = f;
        if (f >= N1) { src = base_m; fr = f - N1; }
        int c  = fr / 9;
        int k  = fr - c * 9;
        int kh = k / 3;
        int kw = k - kh * 3;
        int hh = max(0, min(HW - 1, h + kh - 1));
        int ww = max(0, min(HW - 1, w0 + pix + kw - 1));
        featT[f * FSP + pix] = src[(c * HW + hh) * HW + ww];
    }
    __syncthreads();

    const ull* featT2 = (const ull*)featT;    // [f][18] pixel pairs

    // ============ Phase A: thread owns channel cA (9 taps), 4 pixels ========
    {
        const int cA  = tid & 63;
        const int pgA = tid >> 6;
        ull acc[9][2];
        #pragma unroll
        for (int k = 0; k < 9; k++) { acc[k][0] = 0ull; acc[k][1] = 0ull; }

        const ulonglong2* wq = (const ulonglong2*)W1pd + cA;
        #pragma unroll 2
        for (int f = 0; f < FEAT; f++) {
            const ulonglong2* w = wq + (size_t)f * 320;   // 5*64 per f
            ulonglong2 q0 = w[0];
            ulonglong2 q1 = w[64];
            ulonglong2 q2 = w[128];
            ulonglong2 q3 = w[192];
            ulonglong2 q4 = w[256];
            ulonglong2 vv = *(const ulonglong2*)(featT2 + f * 18 + pgA * 2);
            fma2(acc[0][0], vv.x, q0.x); fma2(acc[0][1], vv.y, q0.x);
            fma2(acc[1][0], vv.x, q0.y); fma2(acc[1][1], vv.y, q0.y);
            fma2(acc[2][0], vv.x, q1.x); fma2(acc[2][1], vv.y, q1.x);
            fma2(acc[3][0], vv.x, q1.y); fma2(acc[3][1], vv.y, q1.y);
            fma2(acc[4][0], vv.x, q2.x); fma2(acc[4][1], vv.y, q2.x);
            fma2(acc[5][0], vv.x, q2.y); fma2(acc[5][1], vv.y, q2.y);
            fma2(acc[6][0], vv.x, q3.x); fma2(acc[6][1], vv.y, q3.x);
            fma2(acc[7][0], vv.x, q3.y); fma2(acc[7][1], vv.y, q3.y);
            fma2(acc[8][0], vv.x, q4.x); fma2(acc[8][1], vv.y, q4.x);
        }

        float yrv[4] = {0,0,0,0}, mrv[4] = {0,0,0,0}, srv[4] = {0,0,0,0};
        #pragma unroll
        for (int k = 0; k < 9; k++) {
            const int j  = cA * 9 + k;
            const float bj = b1[j];
            const int kh = k / 3;
            const int kw = k - kh * 3;
            const int hh = max(0, min(HW - 1, h + kh - 1));
            const float* sp_row = s + (((size_t)b * CIN + cA) * HW + hh) * HW;
            float2 a01 = unpk(acc[k][0]);
            float2 a23 = unpk(acc[k][1]);
            float av[4] = { a01.x, a01.y, a23.x, a23.y };
            #pragma unroll
            for (int p = 0; p < 4; p++) {
                int pix = pgA * 4 + p;
                float v  = av[p] + bj;
                float aw = fabsf(v);
                int ww = max(0, min(HW - 1, w0 + pix + kw - 1));
                yrv[p] += featT[j * FSP + pix] * v;
                mrv[p] += featT[(N1 + j) * FSP + pix] * aw;
                srv[p] += sp_row[ww] * aw;
            }
        }
        #pragma unroll
        for (int p = 0; p < 4; p++) {
            int pix = pgA * 4 + p;
            yr_s[pix * 64 + cA] = yrv[p];
            mr_s[pix * 64 + cA] = mrv[p];
            sr_s[pix * 64 + cA] = srv[p];
        }
    }
    __syncthreads();

    // ============ Phase B: w2 = feat @ W2 + b2, fused channel sum ===========
    const int colB = tid & 127;
    const int pgB  = tid >> 7;
    float ya[8], ma[8], sa[8];
    #pragma unroll
    for (int p = 0; p < 8; p++) { ya[p] = 0.0f; ma[p] = 0.0f; sa[p] = 0.0f; }

    const ulonglong2* w2q = (const ulonglong2*)W2pd;
    for (int cg = 0; cg < 8; cg++) {
        ull acc[4][4];
        #pragma unroll
        for (int i = 0; i < 4; i++)
            #pragma unroll
            for (int pp = 0; pp < 4; pp++) acc[i][pp] = 0ull;

        const ulonglong2* wbase = w2q + ((size_t)cg * FEAT) * 256 + colB;
        #pragma unroll 4
        for (int f = 0; f < FEAT; f++) {
            const ulonglong2* w = wbase + (size_t)f * 256;
            ulonglong2 t0 = w[0];      // cols colB, colB+128 (dup pairs)
            ulonglong2 t1 = w[128];    // cols colB+256, colB+384
            const ulonglong2* fp = (const ulonglong2*)(featT2 + f * 18 + pgB * 4);
            ulonglong2 va = fp[0];
            ulonglong2 vb = fp[1];
            fma2(acc[0][0], va.x, t0.x); fma2(acc[0][1], va.y, t0.x);
            fma2(acc[0][2], vb.x, t0.x); fma2(acc[0][3], vb.y, t0.x);
            fma2(acc[1][0], va.x, t0.y); fma2(acc[1][1], va.y, t0.y);
            fma2(acc[1][2], vb.x, t0.y); fma2(acc[1][3], vb.y, t0.y);
            fma2(acc[2][0], va.x, t1.x); fma2(acc[2][1], va.y, t1.x);
            fma2(acc[2][2], vb.x, t1.x); fma2(acc[2][3], vb.y, t1.x);
            fma2(acc[3][0], va.x, t1.y); fma2(acc[3][1], va.y, t1.y);
            fma2(acc[3][2], vb.x, t1.y); fma2(acc[3][3], vb.y, t1.y);
        }

        #pragma unroll
        for (int i = 0; i < 4; i++) {
            const int j = cg * 512 + colB + i * 128;
            const int c = j >> 6;
            const float bb = b2[j];
            #pragma unroll
            for (int pp = 0; pp < 4; pp++) {
                float2 a = unpk(acc[i][pp]);
                int pixA = pgB * 8 + 2 * pp;
                float yrA = yr_s[pixA * 64 + c], yrB = yr_s[(pixA + 1) * 64 + c];
                float mrA = mr_s[pixA * 64 + c], mrB = mr_s[(pixA + 1) * 64 + c];
                float srA = sr_s[pixA * 64 + c], srB = sr_s[(pixA + 1) * 64 + c];
                float vA = a.x + bb, vB = a.y + bb;
                float aA = fabsf(vA), aB = fabsf(vB);
                ya[2 * pp]     += yrA * vA;  ya[2 * pp + 1] += yrB * vB;
                ma[2 * pp]     += mrA * aA;  ma[2 * pp + 1] += mrB * aB;
                sa[2 * pp]     += srA * aA;  sa[2 * pp + 1] += srB * aB;
            }
        }
    }
    __syncthreads();

    // ============ stage per-half partials, combine, write ===================
    {
        const int half = colB >> 6;
        const int o    = colB & 63;
        float* sty = smf + half * 3 * 2080;   // [32][65] each
        float* stm = sty + 2080;
        float* sts = stm + 2080;
        #pragma unroll
        for (int p = 0; p < 8; p++) {
            int pix = pgB * 8 + p;
            sty[pix * 65 + o] = ya[p];
            stm[pix * 65 + o] = ma[p];
            sts[pix * 65 + o] = sa[p];
        }
    }
    __syncthreads();

    for (int t = tid; t < TILE * CO; t += NTH) {
        int o   = t >> 5;
        int pix = t & 31;
        float y  = smf[pix * 65 + o]             + smf[3 * 2080 + pix * 65 + o];
        float mm = (smf[2080 + pix * 65 + o]     + smf[4 * 2080 + pix * 65 + o]) /
                   (smf[2 * 2080 + pix * 65 + o] + smf[5 * 2080 + pix * 65 + o]);
        size_t gi = (((size_t)b * CO + o) * HW + h) * HW + w0 + pix;
        out[gi]                  = y;
        out[gi + PER_TENSOR]     = mm;
        out[gi + 2 * PER_TENSOR] = 1.0f;
    }
}

extern "C" void kernel_launch(void* const* d_in, const int* in_sizes, int n_in,
                              void* d_out, int out_size)
{
    const float* x  = (const float*)d_in[0];
    const float* m  = (const float*)d_in[1];
    const float* s  = (const float*)d_in[2];
    const float* W1 = (const float*)d_in[3];
    const float* b1 = (const float*)d_in[4];
    const float* W2 = (const float*)d_in[5];
    const float* b2 = (const float*)d_in[6];
    float* out = (float*)d_out;

    cudaFuncSetAttribute(fused_kpn_kernel,
                         cudaFuncAttributeMaxDynamicSharedMemorySize, SMEM_BYTES);

    {
        int n1 = FEAT * 5 * 64 * 4;
        pack_w1<<<(n1 + 255) / 256, 256>>>(W1);
        long long n2 = 8LL * FEAT * 2 * 128 * 4;
        pack_w2<<<(int)((n2 + 255) / 256), 256>>>(W2);
    }

    const int nblocks = (4 * HW * HW) / TILE;   // 2048
    fused_kpn_kernel<<<nblocks, NTH, SMEM_BYTES>>>(x, m, s, b1, b2, out);
}

// round 8
// speedup vs baseline: 2.0183x; 2.0183x over previous
#include <cuda_runtime.h>
#include <cuda_bf16.h>
#include <cstdint>

#define HW 128
#define PER_TENSOR (4 * 64 * HW * HW)
#define NTHP 256
#define NTH  512

// A'': per M-tile (512), 36 chunks (18 hi + 18 lo), each = swizzled
//      [128 pix x 64 k] bf16 tile (16KB).  302 MB.
__device__ __nv_bfloat16 Afeat[(size_t)512 * 36 * 8192];
// B'': pass-major, per pass 54 chunks of [Np x 64 k] swizzled bf16. 32.3 MB.
__device__ __nv_bfloat16 Bpack[(size_t)(3 * 192 + 16 * 256) * 3456];

__device__ __forceinline__ uint32_t swz(uint32_t x) { return x ^ ((x >> 3) & 0x70); }
__device__ __forceinline__ int clampi(int v) { return v < 0 ? 0 : (v > 127 ? 127 : v); }
__device__ __forceinline__ uint32_t smem_u32(const void* p) {
    uint32_t a;
    asm("{ .reg .u64 t; cvta.to.shared.u64 t, %1; cvt.u32.u64 %0, t; }" : "=r"(a) : "l"(p));
    return a;
}
__device__ __forceinline__ void ldsm4(uint32_t& r0, uint32_t& r1, uint32_t& r2, uint32_t& r3, uint32_t a) {
    asm volatile("ldmatrix.sync.aligned.m8n8.x4.shared.b16 {%0,%1,%2,%3}, [%4];"
                 : "=r"(r0), "=r"(r1), "=r"(r2), "=r"(r3) : "r"(a));
}
__device__ __forceinline__ void ldsm2(uint32_t& r0, uint32_t& r1, uint32_t a) {
    asm volatile("ldmatrix.sync.aligned.m8n8.x2.shared.b16 {%0,%1}, [%2];"
                 : "=r"(r0), "=r"(r1) : "r"(a));
}
__device__ __forceinline__ void mma16816(float* d, const uint32_t* a, uint32_t b0, uint32_t b1) {
    asm volatile("mma.sync.aligned.m16n8k16.row.col.f32.bf16.bf16.f32 "
                 "{%0,%1,%2,%3}, {%4,%5,%6,%7}, {%8,%9}, {%0,%1,%2,%3};"
                 : "+f"(d[0]), "+f"(d[1]), "+f"(d[2]), "+f"(d[3])
                 : "r"(a[0]), "r"(a[1]), "r"(a[2]), "r"(a[3]), "r"(b0), "r"(b1));
}
__device__ __forceinline__ void cpa16(uint32_t dst, const void* src) {
    asm volatile("cp.async.cg.shared.global [%0], [%1], 16;" :: "r"(dst), "l"(src) : "memory");
}
#define CP_COMMIT() asm volatile("cp.async.commit_group;" ::: "memory")

// ---------------- prep: feat -> bf16 hi/lo swizzled A tiles ----------------
__global__ void prep_feat(const float* __restrict__ x, const float* __restrict__ m) {
    __shared__ __align__(16) __nv_bfloat16 hi_s[128 * 72];
    __shared__ __align__(16) __nv_bfloat16 lo_s[128 * 72];
    const int fc = blockIdx.x % 18;
    const int mt = blockIdx.x / 18;
    const int b = mt >> 7, hrow = mt & 127;
    const int tid = threadIdx.x;
    for (int idx = tid; idx < 64 * 128; idx += NTHP) {
        int pix = idx & 127, fl = idx >> 7;
        int f = fc * 64 + fl;
        const float* src = x; int fr = f;
        if (f >= 576) { src = m; fr = f - 576; }
        int c = fr / 9, tap = fr - c * 9;
        int kh = tap / 3, kw = tap - kh * 3;
        int hh = clampi(hrow + kh - 1), ww = clampi(pix + kw - 1);
        float v = src[(((size_t)b * 64 + c) * 128 + hh) * 128 + ww];
        __nv_bfloat16 h16 = __float2bfloat16(v);
        hi_s[pix * 72 + fl] = h16;
        lo_s[pix * 72 + fl] = __float2bfloat16(v - __bfloat162float(h16));
    }
    __syncthreads();
    uint4* outh = (uint4*)(Afeat + ((size_t)mt * 36 + fc) * 8192);
    uint4* outl = (uint4*)(Afeat + ((size_t)mt * 36 + fc + 18) * 8192);
    for (int e = tid; e < 1024; e += NTHP) {
        uint32_t u = swz((uint32_t)e * 16);
        int pix = u >> 7, k0 = (u & 127) >> 1;
        outh[e] = *(const uint4*)&hi_s[pix * 72 + k0];
        outl[e] = *(const uint4*)&lo_s[pix * 72 + k0];
    }
}

// ---------------- prep: W1/W2 -> B'' (hi,hi,lo) swizzled, permuted ----------
__global__ void prep_B(const float* __restrict__ W1, const float* __restrict__ W2) {
    __shared__ __align__(16) __nv_bfloat16 hi_s[64 * 72];
    __shared__ __align__(16) __nv_bfloat16 lo_s[64 * 72];
    const int fc = blockIdx.x % 18;
    const int gs = blockIdx.x / 18;           // 0..72
    const int tid = threadIdx.x;
    int p, nn0;
    if (gs < 9) { p = gs / 3; nn0 = (gs % 3) * 64; }
    else        { int t = gs - 9; p = 3 + (t >> 2); nn0 = (t & 3) * 64; }
    const int Np = (p < 3) ? 192 : 256;
    for (int idx = tid; idx < 64 * 64; idx += NTHP) {
        int g_l = idx & 63, kk = idx >> 6;
        int f = fc * 64 + kk;
        int nn = nn0 + g_l;
        float v;
        if (p < 3) { int j = p * 192 + nn; v = W1[(size_t)f * 576 + j]; }
        else { int c = nn >> 2, o = (p - 3) * 4 + (nn & 3); v = W2[(size_t)f * 4096 + c * 64 + o]; }
        __nv_bfloat16 h16 = __float2bfloat16(v);
        hi_s[g_l * 72 + kk] = h16;
        lo_s[g_l * 72 + kk] = __float2bfloat16(v - __bfloat162float(h16));
    }
    __syncthreads();
    const size_t pbase = (p < 3) ? (size_t)p * 192 * 3456
                                 : (size_t)3 * 192 * 3456 + (size_t)(p - 3) * 256 * 3456;
    char* bp = (char*)Bpack;
    const size_t cb0 = (pbase + (size_t)(fc     ) * Np * 64) * 2;
    const size_t cb1 = (pbase + (size_t)(fc + 18) * Np * 64) * 2;
    const size_t cb2 = (pbase + (size_t)(fc + 36) * Np * 64) * 2;
    for (int idx = tid; idx < 512; idx += NTHP) {
        int g_l = idx >> 3, kk0 = (idx & 7) * 8;
        uint32_t q = swz((uint32_t)(nn0 + g_l) * 128 + (uint32_t)kk0 * 2);
        uint4 vh = *(const uint4*)&hi_s[g_l * 72 + kk0];
        uint4 vl = *(const uint4*)&lo_s[g_l * 72 + kk0];
        *(uint4*)(bp + cb0 + q) = vh;
        *(uint4*)(bp + cb1 + q) = vh;
        *(uint4*)(bp + cb2 + q) = vl;
    }
}

// ---------------- main kernel ----------------
#define OFF_A0    0
#define OFF_A1    16384
#define OFF_B0    32768
#define OFF_B1    65536
#define OFF_YR    98304
#define OFF_MR    131584
#define OFF_SR    164864
#define OFF_STAGE 198144
#define SMEM_MAIN 204288

template<int NT8>   // n8 tiles per warp: 3 (Np=192) or 4 (Np=256)
__device__ __forceinline__ void gemm_pass(float (&d)[4][4][4],
    const char* aT, const char* bP, int tid, uint32_t sb)
{
    const int lane = tid & 31, wid = tid >> 5;
    const int wm = wid & 1, wn = wid >> 1;
    #pragma unroll
    for (int mi = 0; mi < 4; mi++)
        #pragma unroll
        for (int ni = 0; ni < NT8; ni++)
            #pragma unroll
            for (int r = 0; r < 4; r++) d[mi][ni][r] = 0.f;

    const uint32_t sA0 = sb + OFF_A0, sA1 = sb + OFF_A1;
    const uint32_t sB0 = sb + OFF_B0, sB1 = sb + OFF_B1;
    const int CB = NT8 * 8192;                 // B chunk bytes

    // preload chunk 0
    #pragma unroll
    for (int i = 0; i < 2; i++)   cpa16(sA0 + (tid + i * NTH) * 16, aT + (size_t)(tid + i * NTH) * 16);
    #pragma unroll
    for (int i = 0; i < NT8; i++) cpa16(sB0 + (tid + i * NTH) * 16, bP + (size_t)(tid + i * NTH) * 16);
    CP_COMMIT();

    const uint32_t aRow  = (uint32_t)((wm * 64 + (lane & 15)) * 128 + (lane >> 4) * 16);
    const uint32_t bRow  = (uint32_t)((wn * (NT8 * 8) + (lane & 15)) * 128 + (lane >> 4) * 16);
    const uint32_t bRow2 = (uint32_t)((wn * 24 + 16 + (lane & 7)) * 128 + ((lane >> 3) & 1) * 16);

    for (int ck = 0; ck < 54; ck++) {
        const int buf = ck & 1;
        if (ck < 53) {
            const int nk = ck + 1, cka = (nk < 36) ? nk : nk - 36;
            const char* aSrc = aT + (size_t)cka * 16384;
            const char* bSrc = bP + (size_t)nk * CB;
            const uint32_t dA = buf ? sA0 : sA1;
            const uint32_t dB = buf ? sB0 : sB1;
            #pragma unroll
            for (int i = 0; i < 2; i++)   cpa16(dA + (tid + i * NTH) * 16, aSrc + (size_t)(tid + i * NTH) * 16);
            #pragma unroll
            for (int i = 0; i < NT8; i++) cpa16(dB + (tid + i * NTH) * 16, bSrc + (size_t)(tid + i * NTH) * 16);
            CP_COMMIT();
            asm volatile("cp.async.wait_group 1;" ::: "memory");
        } else {
            asm volatile("cp.async.wait_group 0;" ::: "memory");
        }
        __syncthreads();
        const uint32_t aB = buf ? sA1 : sA0;
        const uint32_t bB = buf ? sB1 : sB0;
        #pragma unroll
        for (int kg = 0; kg < 4; kg++) {
            const uint32_t kb = kg * 32;
            uint32_t af[4][4];
            #pragma unroll
            for (int mi = 0; mi < 4; mi++)
                ldsm4(af[mi][0], af[mi][1], af[mi][2], af[mi][3],
                      aB + swz(aRow + mi * 2048 + kb));
            uint32_t b0a[4], b1a[4];
            {
                uint32_t r0, r1, r2, r3;
                ldsm4(r0, r1, r2, r3, bB + swz(bRow + kb));
                b0a[0] = r0; b0a[1] = r1; b1a[0] = r2; b1a[1] = r3;
                if (NT8 == 4) {
                    ldsm4(r0, r1, r2, r3, bB + swz(bRow + 2048 + kb));
                    b0a[2] = r0; b0a[3] = r1; b1a[2] = r2; b1a[3] = r3;
                } else {
                    ldsm2(r0, r1, bB + swz(bRow2 + kb));
                    b0a[2] = r0; b1a[2] = r1;
                }
            }
            #pragma unroll
            for (int mi = 0; mi < 4; mi++)
                #pragma unroll
                for (int ni = 0; ni < NT8; ni++)
                    mma16816(d[mi][ni], af[mi], b0a[ni], b1a[ni]);
        }
        __syncthreads();
    }
}

__global__ __launch_bounds__(NTH, 1)
void kpn_main(const float* __restrict__ x, const float* __restrict__ m,
              const float* __restrict__ s, const float* __restrict__ b1,
              const float* __restrict__ b2, float* __restrict__ out)
{
    extern __shared__ __align__(1024) char smc[];
    const uint32_t sb = smem_u32(smc);
    const int tid = threadIdx.x, lane = tid & 31, wid = tid >> 5;
    const int wm = wid & 1, wn = wid >> 1;
    const int mt = blockIdx.x, b = mt >> 7, hrow = mt & 127;

    float* yr_s  = (float*)(smc + OFF_YR);
    float* mr_s  = (float*)(smc + OFF_MR);
    float* sr_s  = (float*)(smc + OFF_SR);
    float* stage = (float*)(smc + OFF_STAGE);
    for (int i = tid; i < 128 * 65; i += NTH) { yr_s[i] = 0.f; mr_s[i] = 0.f; sr_s[i] = 0.f; }
    __syncthreads();

    const char* aT = (const char*)Afeat + (size_t)mt * 36 * 16384;
    float d[4][4][4];

    for (int p = 0; p < 19; p++) {
        if (p < 3) {
            gemm_pass<3>(d, aT, (const char*)Bpack + (size_t)p * 192 * 3456 * 2, tid, sb);
            // ---- W1 epilogue: build yr/mr/sr ----
            #pragma unroll
            for (int mi = 0; mi < 4; mi++) {
                #pragma unroll
                for (int r = 0; r < 4; r++) {
                    const int pix = wm * 64 + mi * 16 + (lane >> 2) + (r >> 1) * 8;
                    #pragma unroll
                    for (int ni = 0; ni < 3; ni++) {
                        const int j = p * 192 + wn * 24 + ni * 8 + (lane & 3) * 2 + (r & 1);
                        const float w1v = d[mi][ni][r] + b1[j];
                        const float aw = fabsf(w1v);
                        const int c = j / 9, tap = j - 9 * c;
                        const int kh = tap / 3, kw = tap - kh * 3;
                        const int hh = clampi(hrow + kh - 1), ww = clampi(pix + kw - 1);
                        const size_t ro = (((size_t)b * 64 + c) * 128 + hh) * 128 + ww;
                        atomicAdd(&yr_s[pix * 65 + c], x[ro] * w1v);
                        atomicAdd(&mr_s[pix * 65 + c], m[ro] * aw);
                        atomicAdd(&sr_s[pix * 65 + c], s[ro] * aw);
                    }
                }
            }
            __syncthreads();
        } else {
            gemm_pass<4>(d, aT,
                (const char*)Bpack + ((size_t)3 * 192 * 3456 + (size_t)(p - 3) * 256 * 3456) * 2,
                tid, sb);
            // ---- W2 epilogue: outputs o = (p-3)*4 + [0,4) ----
            for (int i = tid; i < 128 * 12; i += NTH) stage[i] = 0.f;
            __syncthreads();
            #pragma unroll
            for (int mi = 0; mi < 4; mi++) {
                #pragma unroll
                for (int r = 0; r < 4; r++) {
                    const int pix = wm * 64 + mi * 16 + (lane >> 2) + (r >> 1) * 8;
                    #pragma unroll
                    for (int ni = 0; ni < 4; ni++) {
                        const int nn = wn * 32 + ni * 8 + (lane & 3) * 2 + (r & 1);
                        const int c = nn >> 2, oo = nn & 3;
                        const float v = d[mi][ni][r] + b2[c * 64 + (p - 3) * 4 + oo];
                        const float av = fabsf(v);
                        atomicAdd(&stage[pix * 12 + oo],      yr_s[pix * 65 + c] * v);
                        atomicAdd(&stage[pix * 12 + 4 + oo],  mr_s[pix * 65 + c] * av);
                        atomicAdd(&stage[pix * 12 + 8 + oo],  sr_s[pix * 65 + c] * av);
                    }
                }
            }
            __syncthreads();
            {
                const int px = tid & 127, oo = tid >> 7;
                const int o = (p - 3) * 4 + oo;
                const float y  = stage[px * 12 + oo];
                const float mm = stage[px * 12 + 4 + oo] / stage[px * 12 + 8 + oo];
                const size_t gi = (((size_t)b * 64 + o) * 128 + hrow) * 128 + px;
                out[gi] = y;
                out[gi + PER_TENSOR] = mm;
                out[gi + 2 * PER_TENSOR] = 1.0f;
            }
            __syncthreads();
        }
    }
}

extern "C" void kernel_launch(void* const* d_in, const int* in_sizes, int n_in,
                              void* d_out, int out_size)
{
    const float* x  = (const float*)d_in[0];
    const float* m  = (const float*)d_in[1];
    const float* s  = (const float*)d_in[2];
    const float* W1 = (const float*)d_in[3];
    const float* b1 = (const float*)d_in[4];
    const float* W2 = (const float*)d_in[5];
    const float* b2 = (const float*)d_in[6];
    float* out = (float*)d_out;

    cudaFuncSetAttribute(kpn_main, cudaFuncAttributeMaxDynamicSharedMemorySize, SMEM_MAIN);

    prep_feat<<<512 * 18, NTHP>>>(x, m);
    prep_B<<<73 * 18, NTHP>>>(W1, W2);
    kpn_main<<<512, NTH, SMEM_MAIN>>>(x, m, s, b1, b2, out);
}

// round 9
// speedup vs baseline: 2.0318x; 1.0067x over previous
#include <cuda_runtime.h>
#include <cuda_bf16.h>
#include <cstdint>

#define HW 128
#define PER_TENSOR (4 * 64 * HW * HW)
#define NTHP 256
#define NTH  512

// A'': per M-tile (512), 36 chunks (18 hi + 18 lo), each = swizzled
//      [128 pix x 64 k] bf16 tile (16KB).  302 MB.
__device__ __nv_bfloat16 Afeat[(size_t)512 * 36 * 8192];
// B'': pass-major, per pass 54 chunks of [Np x 64 k] swizzled bf16. 32.3 MB.
__device__ __nv_bfloat16 Bpack[(size_t)(3 * 192 + 16 * 256) * 3456];

__device__ __forceinline__ uint32_t swz(uint32_t x) { return x ^ ((x >> 3) & 0x70); }
__device__ __forceinline__ int clampi(int v) { return v < 0 ? 0 : (v > 127 ? 127 : v); }
__device__ __forceinline__ uint32_t smem_u32(const void* p) {
    uint32_t a;
    asm("{ .reg .u64 t; cvta.to.shared.u64 t, %1; cvt.u32.u64 %0, t; }" : "=r"(a) : "l"(p));
    return a;
}
__device__ __forceinline__ void ldsm4(uint32_t& r0, uint32_t& r1, uint32_t& r2, uint32_t& r3, uint32_t a) {
    asm volatile("ldmatrix.sync.aligned.m8n8.x4.shared.b16 {%0,%1,%2,%3}, [%4];"
                 : "=r"(r0), "=r"(r1), "=r"(r2), "=r"(r3) : "r"(a));
}
__device__ __forceinline__ void ldsm2(uint32_t& r0, uint32_t& r1, uint32_t a) {
    asm volatile("ldmatrix.sync.aligned.m8n8.x2.shared.b16 {%0,%1}, [%2];"
                 : "=r"(r0), "=r"(r1) : "r"(a));
}
__device__ __forceinline__ void mma16816(float* d, const uint32_t* a, uint32_t b0, uint32_t b1) {
    asm volatile("mma.sync.aligned.m16n8k16.row.col.f32.bf16.bf16.f32 "
                 "{%0,%1,%2,%3}, {%4,%5,%6,%7}, {%8,%9}, {%0,%1,%2,%3};"
                 : "+f"(d[0]), "+f"(d[1]), "+f"(d[2]), "+f"(d[3])
                 : "r"(a[0]), "r"(a[1]), "r"(a[2]), "r"(a[3]), "r"(b0), "r"(b1));
}
__device__ __forceinline__ void cpa16(uint32_t dst, const void* src) {
    asm volatile("cp.async.cg.shared.global [%0], [%1], 16;" :: "r"(dst), "l"(src) : "memory");
}
#define CP_COMMIT() asm volatile("cp.async.commit_group;" ::: "memory")
#define CP_WAIT0()  asm volatile("cp.async.wait_group 0;" ::: "memory")

// ---------------- prep: feat -> bf16 hi/lo swizzled A tiles ----------------
__global__ void prep_feat(const float* __restrict__ x, const float* __restrict__ m) {
    __shared__ __align__(16) __nv_bfloat16 hi_s[128 * 72];
    __shared__ __align__(16) __nv_bfloat16 lo_s[128 * 72];
    const int fc = blockIdx.x % 18;
    const int mt = blockIdx.x / 18;
    const int b = mt >> 7, hrow = mt & 127;
    const int tid = threadIdx.x;
    for (int idx = tid; idx < 64 * 128; idx += NTHP) {
        int pix = idx & 127, fl = idx >> 7;
        int f = fc * 64 + fl;
        const float* src = x; int fr = f;
        if (f >= 576) { src = m; fr = f - 576; }
        int c = fr / 9, tap = fr - c * 9;
        int kh = tap / 3, kw = tap - kh * 3;
        int hh = clampi(hrow + kh - 1), ww = clampi(pix + kw - 1);
        float v = src[(((size_t)b * 64 + c) * 128 + hh) * 128 + ww];
        __nv_bfloat16 h16 = __float2bfloat16(v);
        hi_s[pix * 72 + fl] = h16;
        lo_s[pix * 72 + fl] = __float2bfloat16(v - __bfloat162float(h16));
    }
    __syncthreads();
    uint4* outh = (uint4*)(Afeat + ((size_t)mt * 36 + fc) * 8192);
    uint4* outl = (uint4*)(Afeat + ((size_t)mt * 36 + fc + 18) * 8192);
    for (int e = tid; e < 1024; e += NTHP) {
        uint32_t u = swz((uint32_t)e * 16);
        int pix = u >> 7, k0 = (u & 127) >> 1;
        outh[e] = *(const uint4*)&hi_s[pix * 72 + k0];
        outl[e] = *(const uint4*)&lo_s[pix * 72 + k0];
    }
}

// ---------------- prep: W1/W2 -> B'' (hi,hi,lo) swizzled, permuted ----------
__global__ void prep_B(const float* __restrict__ W1, const float* __restrict__ W2) {
    __shared__ __align__(16) __nv_bfloat16 hi_s[64 * 72];
    __shared__ __align__(16) __nv_bfloat16 lo_s[64 * 72];
    const int fc = blockIdx.x % 18;
    const int gs = blockIdx.x / 18;           // 0..72
    const int tid = threadIdx.x;
    int p, nn0;
    if (gs < 9) { p = gs / 3; nn0 = (gs % 3) * 64; }
    else        { int t = gs - 9; p = 3 + (t >> 2); nn0 = (t & 3) * 64; }
    const int Np = (p < 3) ? 192 : 256;
    for (int idx = tid; idx < 64 * 64; idx += NTHP) {
        int g_l = idx & 63, kk = idx >> 6;
        int f = fc * 64 + kk;
        int nn = nn0 + g_l;
        float v;
        if (p < 3) { int j = p * 192 + nn; v = W1[(size_t)f * 576 + j]; }
        else { int c = nn >> 2, o = (p - 3) * 4 + (nn & 3); v = W2[(size_t)f * 4096 + c * 64 + o]; }
        __nv_bfloat16 h16 = __float2bfloat16(v);
        hi_s[g_l * 72 + kk] = h16;
        lo_s[g_l * 72 + kk] = __float2bfloat16(v - __bfloat162float(h16));
    }
    __syncthreads();
    const size_t pbase = (p < 3) ? (size_t)p * 192 * 3456
                                 : (size_t)3 * 192 * 3456 + (size_t)(p - 3) * 256 * 3456;
    char* bp = (char*)Bpack;
    const size_t cb0 = (pbase + (size_t)(fc     ) * Np * 64) * 2;
    const size_t cb1 = (pbase + (size_t)(fc + 18) * Np * 64) * 2;
    const size_t cb2 = (pbase + (size_t)(fc + 36) * Np * 64) * 2;
    for (int idx = tid; idx < 512; idx += NTHP) {
        int g_l = idx >> 3, kk0 = (idx & 7) * 8;
        uint32_t q = swz((uint32_t)(nn0 + g_l) * 128 + (uint32_t)kk0 * 2);
        uint4 vh = *(const uint4*)&hi_s[g_l * 72 + kk0];
        uint4 vl = *(const uint4*)&lo_s[g_l * 72 + kk0];
        *(uint4*)(bp + cb0 + q) = vh;
        *(uint4*)(bp + cb1 + q) = vh;
        *(uint4*)(bp + cb2 + q) = vl;
    }
}

// ---------------- main kernel ----------------
#define OFF_A0    0
#define OFF_A1    16384
#define OFF_B0    32768
#define OFF_B1    65536
#define OFF_YR    98304
#define OFF_MR    131584
#define OFF_SR    164864
#define OFF_STAGE 198144
#define SMEM_MAIN 204288

// Single-sync double-buffered pipeline. Invariant: on entry, this pass's
// chunk 0 has been cp.async-committed into buffer 0 (exactly one group
// outstanding). On exit (when bNext != nullptr), the next pass's chunk 0 is
// committed into buffer 0, overlapping the caller's epilogue.
template<int NT8>   // n8 tiles per warp: 3 (Np=192) or 4 (Np=256)
__device__ __forceinline__ void gemm_pass(float (&d)[4][4][4],
    const char* aT, const char* bP, const char* bNext, int nextNb4,
    int tid, uint32_t sb)
{
    const int lane = tid & 31, wid = tid >> 5;
    const int wm = wid & 1, wn = wid >> 1;
    #pragma unroll
    for (int mi = 0; mi < 4; mi++)
        #pragma unroll
        for (int ni = 0; ni < NT8; ni++)
            #pragma unroll
            for (int r = 0; r < 4; r++) d[mi][ni][r] = 0.f;

    const uint32_t sA0 = sb + OFF_A0, sA1 = sb + OFF_A1;
    const uint32_t sB0 = sb + OFF_B0, sB1 = sb + OFF_B1;
    const int CB = NT8 * 8192;                 // B chunk bytes

    const uint32_t aRow  = (uint32_t)((wm * 64 + (lane & 15)) * 128 + (lane >> 4) * 16);
    const uint32_t bRow  = (uint32_t)((wn * (NT8 * 8) + (lane & 15)) * 128 + (lane >> 4) * 16);
    const uint32_t bRow2 = (uint32_t)((wn * 24 + 16 + (lane & 7)) * 128 + ((lane >> 3) & 1) * 16);

    for (int ck = 0; ck < 54; ck++) {
        const int buf = ck & 1;
        CP_WAIT0();            // current chunk's data resident
        __syncthreads();       // all warps done with the other buffer
        const uint32_t dA = buf ? sA0 : sA1;
        const uint32_t dB = buf ? sB0 : sB1;
        if (ck < 53) {
            const int nk = ck + 1, cka = (nk < 36) ? nk : nk - 36;
            const char* aSrc = aT + (size_t)cka * 16384;
            const char* bSrc = bP + (size_t)nk * CB;
            #pragma unroll
            for (int i = 0; i < 2; i++)   cpa16(dA + (tid + i * NTH) * 16, aSrc + (size_t)(tid + i * NTH) * 16);
            #pragma unroll
            for (int i = 0; i < NT8; i++) cpa16(dB + (tid + i * NTH) * 16, bSrc + (size_t)(tid + i * NTH) * 16);
            CP_COMMIT();
        } else if (bNext) {
            // cross-pass prefetch of next pass's chunk 0 (A chunk 0 = hi[0])
            #pragma unroll
            for (int i = 0; i < 2; i++) cpa16(dA + (tid + i * NTH) * 16, aT + (size_t)(tid + i * NTH) * 16);
            for (int i = 0; i < nextNb4; i++) cpa16(dB + (tid + i * NTH) * 16, bNext + (size_t)(tid + i * NTH) * 16);
            CP_COMMIT();
        }
        const uint32_t aB = buf ? sA1 : sA0;
        const uint32_t bB = buf ? sB1 : sB0;
        #pragma unroll
        for (int kg = 0; kg < 4; kg++) {
            const uint32_t kb = kg * 32;
            uint32_t af[4][4];
            #pragma unroll
            for (int mi = 0; mi < 4; mi++)
                ldsm4(af[mi][0], af[mi][1], af[mi][2], af[mi][3],
                      aB + swz(aRow + mi * 2048 + kb));
            uint32_t b0a[4], b1a[4];
            {
                uint32_t r0, r1, r2, r3;
                ldsm4(r0, r1, r2, r3, bB + swz(bRow + kb));
                b0a[0] = r0; b0a[1] = r1; b1a[0] = r2; b1a[1] = r3;
                if (NT8 == 4) {
                    ldsm4(r0, r1, r2, r3, bB + swz(bRow + 2048 + kb));
                    b0a[2] = r0; b0a[3] = r1; b1a[2] = r2; b1a[3] = r3;
                } else {
                    ldsm2(r0, r1, bB + swz(bRow2 + kb));
                    b0a[2] = r0; b1a[2] = r1;
                }
            }
            #pragma unroll
            for (int mi = 0; mi < 4; mi++)
                #pragma unroll
                for (int ni = 0; ni < NT8; ni++)
                    mma16816(d[mi][ni], af[mi], b0a[ni], b1a[ni]);
        }
    }
}

__device__ __forceinline__ const char* bbase(int p) {
    return (const char*)Bpack + ((p < 3) ? (size_t)p * 192 * 3456
                                         : (size_t)3 * 192 * 3456 + (size_t)(p - 3) * 256 * 3456) * 2;
}

__global__ __launch_bounds__(NTH, 1)
void kpn_main(const float* __restrict__ x, const float* __restrict__ m,
              const float* __restrict__ s, const float* __restrict__ b1,
              const float* __restrict__ b2, float* __restrict__ out)
{
    extern __shared__ __align__(1024) char smc[];
    const uint32_t sb = smem_u32(smc);
    const int tid = threadIdx.x, lane = tid & 31, wid = tid >> 5;
    const int wm = wid & 1, wn = wid >> 1;
    const int mt = blockIdx.x, b = mt >> 7, hrow = mt & 127;

    const char* aT = (const char*)Afeat + (size_t)mt * 36 * 16384;

    // preload pass 0 chunk 0 into buffer 0 (overlaps the smem zeroing below)
    {
        const char* bSrc = bbase(0);
        #pragma unroll
        for (int i = 0; i < 2; i++) cpa16(sb + OFF_A0 + (tid + i * NTH) * 16, aT + (size_t)(tid + i * NTH) * 16);
        #pragma unroll
        for (int i = 0; i < 3; i++) cpa16(sb + OFF_B0 + (tid + i * NTH) * 16, bSrc + (size_t)(tid + i * NTH) * 16);
        CP_COMMIT();
    }

    float* yr_s  = (float*)(smc + OFF_YR);
    float* mr_s  = (float*)(smc + OFF_MR);
    float* sr_s  = (float*)(smc + OFF_SR);
    float* stage = (float*)(smc + OFF_STAGE);
    for (int i = tid; i < 128 * 65; i += NTH) { yr_s[i] = 0.f; mr_s[i] = 0.f; sr_s[i] = 0.f; }

    float d[4][4][4];

    for (int p = 0; p < 19; p++) {
        if (p < 3) {
            gemm_pass<3>(d, aT, bbase(p), bbase(p + 1), (p + 1 < 3) ? 3 : 4, tid, sb);
            // ---- W1 epilogue: build yr/mr/sr ----
            #pragma unroll
            for (int mi = 0; mi < 4; mi++) {
                #pragma unroll
                for (int r = 0; r < 4; r++) {
                    const int pix = wm * 64 + mi * 16 + (lane >> 2) + (r >> 1) * 8;
                    #pragma unroll
                    for (int ni = 0; ni < 3; ni++) {
                        const int j = p * 192 + wn * 24 + ni * 8 + (lane & 3) * 2 + (r & 1);
                        const float w1v = d[mi][ni][r] + b1[j];
                        const float aw = fabsf(w1v);
                        const int c = j / 9, tap = j - 9 * c;
                        const int kh = tap / 3, kw = tap - kh * 3;
                        const int hh = clampi(hrow + kh - 1), ww = clampi(pix + kw - 1);
                        const size_t ro = (((size_t)b * 64 + c) * 128 + hh) * 128 + ww;
                        atomicAdd(&yr_s[pix * 65 + c], x[ro] * w1v);
                        atomicAdd(&mr_s[pix * 65 + c], m[ro] * aw);
                        atomicAdd(&sr_s[pix * 65 + c], s[ro] * aw);
                    }
                }
            }
            __syncthreads();
        } else {
            gemm_pass<4>(d, aT, bbase(p), (p < 18) ? bbase(p + 1) : nullptr, 4, tid, sb);
            // ---- W2 epilogue: outputs o = (p-3)*4 + [0,4) ----
            for (int i = tid; i < 128 * 12; i += NTH) stage[i] = 0.f;
            __syncthreads();
            #pragma unroll
            for (int mi = 0; mi < 4; mi++) {
                #pragma unroll
                for (int r = 0; r < 4; r++) {
                    const int pix = wm * 64 + mi * 16 + (lane >> 2) + (r >> 1) * 8;
                    #pragma unroll
                    for (int ni = 0; ni < 4; ni++) {
                        const int nn = wn * 32 + ni * 8 + (lane & 3) * 2 + (r & 1);
                        const int c = nn >> 2, oo = nn & 3;
                        const float v = d[mi][ni][r] + b2[c * 64 + (p - 3) * 4 + oo];
                        const float av = fabsf(v);
                        atomicAdd(&stage[pix * 12 + oo],      yr_s[pix * 65 + c] * v);
                        atomicAdd(&stage[pix * 12 + 4 + oo],  mr_s[pix * 65 + c] * av);
                        atomicAdd(&stage[pix * 12 + 8 + oo],  sr_s[pix * 65 + c] * av);
                    }
                }
            }
            __syncthreads();
            {
                const int px = tid & 127, oo = tid >> 7;
                const int o = (p - 3) * 4 + oo;
                const float y  = stage[px * 12 + oo];
                const float mm = stage[px * 12 + 4 + oo] / stage[px * 12 + 8 + oo];
                const size_t gi = (((size_t)b * 64 + o) * 128 + hrow) * 128 + px;
                out[gi] = y;
                out[gi + PER_TENSOR] = mm;
                out[gi + 2 * PER_TENSOR] = 1.0f;
            }
            __syncthreads();
        }
    }
}

extern "C" void kernel_launch(void* const* d_in, const int* in_sizes, int n_in,
                              void* d_out, int out_size)
{
    const float* x  = (const float*)d_in[0];
    const float* m  = (const float*)d_in[1];
    const float* s  = (const float*)d_in[2];
    const float* W1 = (const float*)d_in[3];
    const float* b1 = (const float*)d_in[4];
    const float* W2 = (const float*)d_in[5];
    const float* b2 = (const float*)d_in[6];
    float* out = (float*)d_out;

    cudaFuncSetAttribute(kpn_main, cudaFuncAttributeMaxDynamicSharedMemorySize, SMEM_MAIN);

    prep_feat<<<512 * 18, NTHP>>>(x, m);
    prep_B<<<73 * 18, NTHP>>>(W1, W2);
    kpn_main<<<512, NTH, SMEM_MAIN>>>(x, m, s, b1, b2, out);
}

// round 10
// speedup vs baseline: 2.0328x; 1.0005x over previous
#include <cuda_runtime.h>
#include <cuda_bf16.h>
#include <cstdint>

#define HW 128
#define PER_TENSOR (4 * 64 * HW * HW)
#define NTHP 256
#define NTH  512

// A'': per M-tile (512), 36 chunks (18 hi + 18 lo), each = swizzled
//      [128 pix x 64 k] bf16 tile (16KB).  302 MB.
__device__ __nv_bfloat16 Afeat[(size_t)512 * 36 * 8192];
// B'': pass-major, per pass 54 chunks of [Np x 64 k] swizzled bf16. 32.3 MB.
__device__ __nv_bfloat16 Bpack[(size_t)(3 * 192 + 16 * 256) * 3456];

__device__ __forceinline__ uint32_t swz(uint32_t x) { return x ^ ((x >> 3) & 0x70); }
__device__ __forceinline__ int clampi(int v) { return v < 0 ? 0 : (v > 127 ? 127 : v); }
__device__ __forceinline__ uint32_t smem_u32(const void* p) {
    uint32_t a;
    asm("{ .reg .u64 t; cvta.to.shared.u64 t, %1; cvt.u32.u64 %0, t; }" : "=r"(a) : "l"(p));
    return a;
}
__device__ __forceinline__ void ldsm4(uint32_t& r0, uint32_t& r1, uint32_t& r2, uint32_t& r3, uint32_t a) {
    asm volatile("ldmatrix.sync.aligned.m8n8.x4.shared.b16 {%0,%1,%2,%3}, [%4];"
                 : "=r"(r0), "=r"(r1), "=r"(r2), "=r"(r3) : "r"(a));
}
__device__ __forceinline__ void ldsm2(uint32_t& r0, uint32_t& r1, uint32_t a) {
    asm volatile("ldmatrix.sync.aligned.m8n8.x2.shared.b16 {%0,%1}, [%2];"
                 : "=r"(r0), "=r"(r1) : "r"(a));
}
__device__ __forceinline__ void mma16816(float* d, const uint32_t* a, uint32_t b0, uint32_t b1) {
    asm volatile("mma.sync.aligned.m16n8k16.row.col.f32.bf16.bf16.f32 "
                 "{%0,%1,%2,%3}, {%4,%5,%6,%7}, {%8,%9}, {%0,%1,%2,%3};"
                 : "+f"(d[0]), "+f"(d[1]), "+f"(d[2]), "+f"(d[3])
                 : "r"(a[0]), "r"(a[1]), "r"(a[2]), "r"(a[3]), "r"(b0), "r"(b1));
}
__device__ __forceinline__ void cpa16(uint32_t dst, const void* src) {
    asm volatile("cp.async.cg.shared.global [%0], [%1], 16;" :: "r"(dst), "l"(src) : "memory");
}
#define CP_COMMIT() asm volatile("cp.async.commit_group;" ::: "memory")
#define CP_WAIT0()  asm volatile("cp.async.wait_group 0;" ::: "memory")

// ---------------- prep: feat -> bf16 hi/lo swizzled A tiles ----------------
__global__ void prep_feat(const float* __restrict__ x, const float* __restrict__ m) {
    __shared__ __align__(16) __nv_bfloat16 hi_s[128 * 72];
    __shared__ __align__(16) __nv_bfloat16 lo_s[128 * 72];
    const int fc = blockIdx.x % 18;
    const int mt = blockIdx.x / 18;
    const int b = mt >> 7, hrow = mt & 127;
    const int tid = threadIdx.x;
    for (int idx = tid; idx < 64 * 128; idx += NTHP) {
        int pix = idx & 127, fl = idx >> 7;
        int f = fc * 64 + fl;
        const float* src = x; int fr = f;
        if (f >= 576) { src = m; fr = f - 576; }
        int c = fr / 9, tap = fr - c * 9;
        int kh = tap / 3, kw = tap - kh * 3;
        int hh = clampi(hrow + kh - 1), ww = clampi(pix + kw - 1);
        float v = src[(((size_t)b * 64 + c) * 128 + hh) * 128 + ww];
        __nv_bfloat16 h16 = __float2bfloat16(v);
        hi_s[pix * 72 + fl] = h16;
        lo_s[pix * 72 + fl] = __float2bfloat16(v - __bfloat162float(h16));
    }
    __syncthreads();
    uint4* outh = (uint4*)(Afeat + ((size_t)mt * 36 + fc) * 8192);
    uint4* outl = (uint4*)(Afeat + ((size_t)mt * 36 + fc + 18) * 8192);
    for (int e = tid; e < 1024; e += NTHP) {
        uint32_t u = swz((uint32_t)e * 16);
        int pix = u >> 7, k0 = (u & 127) >> 1;
        outh[e] = *(const uint4*)&hi_s[pix * 72 + k0];
        outl[e] = *(const uint4*)&lo_s[pix * 72 + k0];
    }
}

// ---------------- prep: W1/W2 -> B'' (hi,hi,lo) swizzled, permuted ----------
__global__ void prep_B(const float* __restrict__ W1, const float* __restrict__ W2) {
    __shared__ __align__(16) __nv_bfloat16 hi_s[64 * 72];
    __shared__ __align__(16) __nv_bfloat16 lo_s[64 * 72];
    const int fc = blockIdx.x % 18;
    const int gs = blockIdx.x / 18;           // 0..72
    const int tid = threadIdx.x;
    int p, nn0;
    if (gs < 9) { p = gs / 3; nn0 = (gs % 3) * 64; }
    else        { int t = gs - 9; p = 3 + (t >> 2); nn0 = (t & 3) * 64; }
    const int Np = (p < 3) ? 192 : 256;
    for (int idx = tid; idx < 64 * 64; idx += NTHP) {
        int g_l = idx & 63, kk = idx >> 6;
        int f = fc * 64 + kk;
        int nn = nn0 + g_l;
        float v;
        if (p < 3) { int j = p * 192 + nn; v = W1[(size_t)f * 576 + j]; }
        else { int c = nn >> 2, o = (p - 3) * 4 + (nn & 3); v = W2[(size_t)f * 4096 + c * 64 + o]; }
        __nv_bfloat16 h16 = __float2bfloat16(v);
        hi_s[g_l * 72 + kk] = h16;
        lo_s[g_l * 72 + kk] = __float2bfloat16(v - __bfloat162float(h16));
    }
    __syncthreads();
    const size_t pbase = (p < 3) ? (size_t)p * 192 * 3456
                                 : (size_t)3 * 192 * 3456 + (size_t)(p - 3) * 256 * 3456;
    char* bp = (char*)Bpack;
    const size_t cb0 = (pbase + (size_t)(fc     ) * Np * 64) * 2;
    const size_t cb1 = (pbase + (size_t)(fc + 18) * Np * 64) * 2;
    const size_t cb2 = (pbase + (size_t)(fc + 36) * Np * 64) * 2;
    for (int idx = tid; idx < 512; idx += NTHP) {
        int g_l = idx >> 3, kk0 = (idx & 7) * 8;
        uint32_t q = swz((uint32_t)(nn0 + g_l) * 128 + (uint32_t)kk0 * 2);
        uint4 vh = *(const uint4*)&hi_s[g_l * 72 + kk0];
        uint4 vl = *(const uint4*)&lo_s[g_l * 72 + kk0];
        *(uint4*)(bp + cb0 + q) = vh;
        *(uint4*)(bp + cb1 + q) = vh;
        *(uint4*)(bp + cb2 + q) = vl;
    }
}

// ---------------- main kernel ----------------
#define OFF_A0    0
#define OFF_A1    16384
#define OFF_B0    32768
#define OFF_B1    65536
#define OFF_YR    98304
#define OFF_MR    131584
#define OFF_SR    164864
#define OFF_STAGE 198144
#define SMEM_MAIN 204288

// Single-sync double-buffered pipeline. Invariant: on entry, this pass's
// chunk 0 has been cp.async-committed into buffer 0 (exactly one group
// outstanding). On exit (when bNext != nullptr), the next pass's chunk 0 is
// committed into buffer 0, overlapping the caller's epilogue.
template<int NT8>   // n8 tiles per warp: 3 (Np=192) or 4 (Np=256)
__device__ __forceinline__ void gemm_pass(float (&d)[4][4][4],
    const char* aT, const char* bP, const char* bNext, int nextNb4,
    int tid, uint32_t sb)
{
    const int lane = tid & 31, wid = tid >> 5;
    const int wm = wid & 1, wn = wid >> 1;
    #pragma unroll
    for (int mi = 0; mi < 4; mi++)
        #pragma unroll
        for (int ni = 0; ni < NT8; ni++)
            #pragma unroll
            for (int r = 0; r < 4; r++) d[mi][ni][r] = 0.f;

    const uint32_t sA0 = sb + OFF_A0, sA1 = sb + OFF_A1;
    const uint32_t sB0 = sb + OFF_B0, sB1 = sb + OFF_B1;
    const int CB = NT8 * 8192;                 // B chunk bytes

    const uint32_t aRow  = (uint32_t)((wm * 64 + (lane & 15)) * 128 + (lane >> 4) * 16);
    const uint32_t bRow  = (uint32_t)((wn * (NT8 * 8) + (lane & 15)) * 128 + (lane >> 4) * 16);
    const uint32_t bRow2 = (uint32_t)((wn * 24 + 16 + (lane & 7)) * 128 + ((lane >> 3) & 1) * 16);

    for (int ck = 0; ck < 54; ck++) {
        const int buf = ck & 1;
        CP_WAIT0();            // current chunk's data resident
        __syncthreads();       // all warps done with the other buffer
        const uint32_t dA = buf ? sA0 : sA1;
        const uint32_t dB = buf ? sB0 : sB1;
        if (ck < 53) {
            const int nk = ck + 1, cka = (nk < 36) ? nk : nk - 36;
            const char* aSrc = aT + (size_t)cka * 16384;
            const char* bSrc = bP + (size_t)nk * CB;
            #pragma unroll
            for (int i = 0; i < 2; i++)   cpa16(dA + (tid + i * NTH) * 16, aSrc + (size_t)(tid + i * NTH) * 16);
            #pragma unroll
            for (int i = 0; i < NT8; i++) cpa16(dB + (tid + i * NTH) * 16, bSrc + (size_t)(tid + i * NTH) * 16);
            CP_COMMIT();
        } else if (bNext) {
            // cross-pass prefetch of next pass's chunk 0 (A chunk 0 = hi[0])
            #pragma unroll
            for (int i = 0; i < 2; i++) cpa16(dA + (tid + i * NTH) * 16, aT + (size_t)(tid + i * NTH) * 16);
            for (int i = 0; i < nextNb4; i++) cpa16(dB + (tid + i * NTH) * 16, bNext + (size_t)(tid + i * NTH) * 16);
            CP_COMMIT();
        }
        const uint32_t aB = buf ? sA1 : sA0;
        const uint32_t bB = buf ? sB1 : sB0;
        #pragma unroll
        for (int kg = 0; kg < 4; kg++) {
            const uint32_t kb = kg * 32;
            uint32_t af[4][4];
            #pragma unroll
            for (int mi = 0; mi < 4; mi++)
                ldsm4(af[mi][0], af[mi][1], af[mi][2], af[mi][3],
                      aB + swz(aRow + mi * 2048 + kb));
            uint32_t b0a[4], b1a[4];
            {
                uint32_t r0, r1, r2, r3;
                ldsm4(r0, r1, r2, r3, bB + swz(bRow + kb));
                b0a[0] = r0; b0a[1] = r1; b1a[0] = r2; b1a[1] = r3;
                if (NT8 == 4) {
                    ldsm4(r0, r1, r2, r3, bB + swz(bRow + 2048 + kb));
                    b0a[2] = r0; b0a[3] = r1; b1a[2] = r2; b1a[3] = r3;
                } else {
                    ldsm2(r0, r1, bB + swz(bRow2 + kb));
                    b0a[2] = r0; b1a[2] = r1;
                }
            }
            #pragma unroll
            for (int mi = 0; mi < 4; mi++)
                #pragma unroll
                for (int ni = 0; ni < NT8; ni++)
                    mma16816(d[mi][ni], af[mi], b0a[ni], b1a[ni]);
        }
    }
}

__device__ __forceinline__ const char* bbase(int p) {
    return (const char*)Bpack + ((p < 3) ? (size_t)p * 192 * 3456
                                         : (size_t)3 * 192 * 3456 + (size_t)(p - 3) * 256 * 3456) * 2;
}

__global__ __launch_bounds__(NTH, 1)
void kpn_main(const float* __restrict__ x, const float* __restrict__ m,
              const float* __restrict__ s, const float* __restrict__ b1,
              const float* __restrict__ b2, float* __restrict__ out)
{
    extern __shared__ __align__(1024) char smc[];
    const uint32_t sb = smem_u32(smc);
    const int tid = threadIdx.x, lane = tid & 31, wid = tid >> 5;
    const int wm = wid & 1, wn = wid >> 1;
    const int mt = blockIdx.x, b = mt >> 7, hrow = mt & 127;

    const char* aT = (const char*)Afeat + (size_t)mt * 36 * 16384;

    // preload pass 0 chunk 0 into buffer 0 (overlaps the smem zeroing below)
    {
        const char* bSrc = bbase(0);
        #pragma unroll
        for (int i = 0; i < 2; i++) cpa16(sb + OFF_A0 + (tid + i * NTH) * 16, aT + (size_t)(tid + i * NTH) * 16);
        #pragma unroll
        for (int i = 0; i < 3; i++) cpa16(sb + OFF_B0 + (tid + i * NTH) * 16, bSrc + (size_t)(tid + i * NTH) * 16);
        CP_COMMIT();
    }

    float* yr_s  = (float*)(smc + OFF_YR);
    float* mr_s  = (float*)(smc + OFF_MR);
    float* sr_s  = (float*)(smc + OFF_SR);
    float* stage = (float*)(smc + OFF_STAGE);
    for (int i = tid; i < 128 * 65; i += NTH) { yr_s[i] = 0.f; mr_s[i] = 0.f; sr_s[i] = 0.f; }

    float d[4][4][4];

    for (int p = 0; p < 19; p++) {
        if (p < 3) {
            gemm_pass<3>(d, aT, bbase(p), bbase(p + 1), (p + 1 < 3) ? 3 : 4, tid, sb);
            // ---- W1 epilogue: build yr/mr/sr ----
            #pragma unroll
            for (int mi = 0; mi < 4; mi++) {
                #pragma unroll
                for (int r = 0; r < 4; r++) {
                    const int pix = wm * 64 + mi * 16 + (lane >> 2) + (r >> 1) * 8;
                    #pragma unroll
                    for (int ni = 0; ni < 3; ni++) {
                        const int j = p * 192 + wn * 24 + ni * 8 + (lane & 3) * 2 + (r & 1);
                        const float w1v = d[mi][ni][r] + b1[j];
                        const float aw = fabsf(w1v);
                        const int c = j / 9, tap = j - 9 * c;
                        const int kh = tap / 3, kw = tap - kh * 3;
                        const int hh = clampi(hrow + kh - 1), ww = clampi(pix + kw - 1);
                        const size_t ro = (((size_t)b * 64 + c) * 128 + hh) * 128 + ww;
                        atomicAdd(&yr_s[pix * 65 + c], x[ro] * w1v);
                        atomicAdd(&mr_s[pix * 65 + c], m[ro] * aw);
                        atomicAdd(&sr_s[pix * 65 + c], s[ro] * aw);
                    }
                }
            }
            __syncthreads();
        } else {
            gemm_pass<4>(d, aT, bbase(p), (p < 18) ? bbase(p + 1) : nullptr, 4, tid, sb);
            // ---- W2 epilogue: outputs o = (p-3)*4 + [0,4) ----
            for (int i = tid; i < 128 * 12; i += NTH) stage[i] = 0.f;
            __syncthreads();
            #pragma unroll
            for (int mi = 0; mi < 4; mi++) {
                #pragma unroll
                for (int r = 0; r < 4; r++) {
                    const int pix = wm * 64 + mi * 16 + (lane >> 2) + (r >> 1) * 8;
                    #pragma unroll
                    for (int ni = 0; ni < 4; ni++) {
                        const int nn = wn * 32 + ni * 8 + (lane & 3) * 2 + (r & 1);
                        const int c = nn >> 2, oo = nn & 3;
                        const float v = d[mi][ni][r] + b2[c * 64 + (p - 3) * 4 + oo];
                        const float av = fabsf(v);
                        atomicAdd(&stage[pix * 12 + oo],      yr_s[pix * 65 + c] * v);
                        atomicAdd(&stage[pix * 12 + 4 + oo],  mr_s[pix * 65 + c] * av);
                        atomicAdd(&stage[pix * 12 + 8 + oo],  sr_s[pix * 65 + c] * av);
                    }
                }
            }
            __syncthreads();
            {
                const int px = tid & 127, oo = tid >> 7;
                const int o = (p - 3) * 4 + oo;
                const float y  = stage[px * 12 + oo];
                const float mm = stage[px * 12 + 4 + oo] / stage[px * 12 + 8 + oo];
                const size_t gi = (((size_t)b * 64 + o) * 128 + hrow) * 128 + px;
                out[gi] = y;
                out[gi + PER_TENSOR] = mm;
                out[gi + 2 * PER_TENSOR] = 1.0f;
            }
            __syncthreads();
        }
    }
}

extern "C" void kernel_launch(void* const* d_in, const int* in_sizes, int n_in,
                              void* d_out, int out_size)
{
    const float* x  = (const float*)d_in[0];
    const float* m  = (const float*)d_in[1];
    const float* s  = (const float*)d_in[2];
    const float* W1 = (const float*)d_in[3];
    const float* b1 = (const float*)d_in[4];
    const float* W2 = (const float*)d_in[5];
    const float* b2 = (const float*)d_in[6];
    float* out = (float*)d_out;

    cudaFuncSetAttribute(kpn_main, cudaFuncAttributeMaxDynamicSharedMemorySize, SMEM_MAIN);

    prep_feat<<<512 * 18, NTHP>>>(x, m);
    prep_B<<<73 * 18, NTHP>>>(W1, W2);
    kpn_main<<<512, NTH, SMEM_MAIN>>>(x, m, s, b1, b2, out);
}